// round 14
// baseline (speedup 1.0000x reference)
#include <cuda_runtime.h>
#include <cstdint>

#define BATCH 16
#define NPRED 22743
#define NCH   85
#define NCLS  80
#define TOPK  1000
#define CAND_CAP 2048
#define FULLMASK 0xFFFFFFFFu
#define NPRED_UP 23552
#define NROWS (BATCH * NPRED)
#define HBINS 16384            // key top-16 bits minus 0x8000, score>0 only
#define RIDX(d) ((d) + ((d) >> 4))   // pad: stride-17 -> conflict-free

// ---------------- device scratch (no allocations allowed) ----------------
__device__ __align__(16) unsigned long long g_keys[NROWS];
__device__ float    g_conf[NROWS];          // valid for positive rows only
__device__ int      g_cls [NROWS];          // valid for positive rows only
__device__ __align__(16) unsigned g_hist[BATCH * HBINS]; // zero-init; nms re-zeroes

#define NEG_HI 0x407FFFFFu     // ord32(-1.0f)

__device__ __forceinline__ unsigned ord32(float f) {
    unsigned u = __float_as_uint(f);
    return (u & 0x80000000u) ? ~u : (u | 0x80000000u);
}

// ---------------- kernel A: obj-gated score / cls / key / hist ------------
#define TA 256
__global__ void score_kernel(const float* __restrict__ in) {
    __shared__ unsigned short s_list[TA];
    __shared__ float          s_obj [TA];
    __shared__ int s_np;
    const int R0  = blockIdx.x * TA;
    const int tid = threadIdx.x;
    const int lane = tid & 31, warp = tid >> 5;
    if (tid == 0) s_np = 0;
    __syncthreads();

    int gr = R0 + tid;
    bool inr = gr < NROWS;
    float obj = inr ? in[(size_t)gr * NCH + 4] : 0.0f;
    bool pos = inr && (obj >= 0.5f);
    if (inr && !pos) {                      // finish negative rows now
        int b = gr / NPRED;
        unsigned n = (unsigned)(gr - b * NPRED);
        g_keys[gr] = ((unsigned long long)NEG_HI << 32) | (unsigned)(~n);
    }
    unsigned bm = __ballot_sync(FULLMASK, pos);
    unsigned base = 0;
    if (lane == 0 && bm) base = atomicAdd(&s_np, __popc(bm));
    base = __shfl_sync(FULLMASK, base, 0);
    if (pos) s_list[base + __popc(bm & ((1u << lane) - 1u))] = (unsigned short)tid;
    s_obj[tid] = obj;
    __syncthreads();

    const int np = s_np;
    for (int i = warp; i < np; i += TA / 32) {
        int lt = (int)s_list[i];
        int r  = R0 + lt;
        const float* row = in + (size_t)r * NCH;
        unsigned u0 = __float_as_uint(row[5  + lane]);
        unsigned u1 = __float_as_uint(row[37 + lane]);
        unsigned u2 = (lane < 16) ? __float_as_uint(row[69 + lane]) : 0u;
        unsigned m  = __reduce_max_sync(FULLMASK, max(u0, max(u1, u2)));
        unsigned cd = (u0 == m) ? (unsigned)lane
                    : (u1 == m) ? (unsigned)(lane + 32)
                    : ((lane < 16) && (u2 == m)) ? (unsigned)(lane + 64) : 1024u;
        unsigned ci = __reduce_min_sync(FULLMASK, cd);
        if (lane == 0) {
            float conf  = __uint_as_float(m);
            float score = __fmul_rn(s_obj[lt], conf);   // obj >= 0.5 here
            int b = r / NPRED;
            unsigned n = (unsigned)(r - b * NPRED);
            unsigned long long key =
                ((unsigned long long)ord32(score) << 32) | (unsigned)(~n);
            g_keys[r] = key;
            g_conf[r] = conf;
            g_cls [r] = (int)ci;
            if (score > 0.0f)
                atomicAdd(&g_hist[b * HBINS + (int)((key >> 48) - 0x8000u)], 1u);
        }
    }
}

// ---------------- kernel B: rank-scatter select + per-class NMS -----------
// SMEM layout (bytes, cumulative):
//   skeys 16384 -> 16384 | sbox 16384 -> 32768 | rankS 69632 -> 102400 |
//   sarea 4096 -> 106496 | sobj 4096 -> 110592 | sconf 4096 -> 114688 |
//   scls 4096 -> 118784 | ccnt 512 -> 119296 | coff 512 -> 119808 |
//   wtot 128 -> 119936 | wexcl 128 -> 120064 | clist 2048 -> 122112 |
//   keepf 1024 -> 123136
#define SMEM_B 123136

__global__ void __launch_bounds__(1024, 1)
nms_kernel(const float* __restrict__ in, float* __restrict__ out) {
    extern __shared__ unsigned char smem_raw[];
    unsigned long long* skeys = (unsigned long long*)smem_raw;          // [2048]
    float4*             sbox  = (float4*)(skeys + CAND_CAP);            // [1024]
    unsigned*           rankS = (unsigned*)(sbox + 1024);               // [17408]
    float*              sarea = (float*)(rankS + 17408);                // [1024]
    float*              sobj  = sarea + 1024;                           // [1024]
    float*              sconf = sobj + 1024;                            // [1024]
    int*                scls  = (int*)(sconf + 1024);                   // [1024]
    unsigned*           ccnt  = (unsigned*)(scls + 1024);               // [128]
    unsigned*           coff  = ccnt + 128;                             // [128]
    unsigned*           wtot  = coff + 128;                             // [32]
    unsigned*           wexcl = wtot + 32;                              // [32]
    unsigned short*     clist = (unsigned short*)(wexcl + 32);          // [1024]
    unsigned char*      keepf = (unsigned char*)(clist + 1024);         // [1024]
    unsigned*           whist = rankS;   // fallback alias (32*256 u32)

    __shared__ int s_found, s_bin, s_fb, s_cnt, s_r, s_done, s_flag;
    __shared__ unsigned s_cntge;
    __shared__ unsigned long long s_prefix;

    const int b    = blockIdx.x;
    const int tid  = threadIdx.x;
    const int lane = tid & 31;
    const int warp = tid >> 5;
    const unsigned long long* keys = g_keys + (size_t)b * NPRED;
    unsigned* hb = g_hist + b * HBINS;

    if (tid == 0) { s_found = 0; s_fb = 0; s_cnt = 0; }
    if (tid < 128) ccnt[tid] = 0u;
    __syncthreads();

    // ==== Phase 1: hist suffix-scan -> per-bin base ranks + threshold ====
    // thread t owns bins [t*16, t*16+16)
    unsigned c[16];
    {
        const uint4* hb4 = (const uint4*)hb;
        #pragma unroll
        for (int i = 0; i < 4; ++i) {
            uint4 h = hb4[tid * 4 + i];
            c[i*4] = h.x; c[i*4+1] = h.y; c[i*4+2] = h.z; c[i*4+3] = h.w;
        }
    }
    unsigned part = 0;
    #pragma unroll
    for (int i = 0; i < 16; ++i) part += c[i];
    unsigned incl = part;                      // warp suffix-inclusive
    #pragma unroll
    for (int off = 1; off < 32; off <<= 1) {
        unsigned o = __shfl_down_sync(FULLMASK, incl, off);
        if (lane + off < 32) incl += o;
    }
    if (lane == 0) wtot[warp] = incl;
    __syncthreads();
    if (warp == 0) {
        unsigned t = wtot[lane];
        unsigned i2 = t;
        #pragma unroll
        for (int off = 1; off < 32; off <<= 1) {
            unsigned o = __shfl_down_sync(FULLMASK, i2, off);
            if (lane + off < 32) i2 += o;
        }
        wexcl[lane] = i2 - t;
    }
    __syncthreads();
    {
        unsigned running = wexcl[warp] + (incl - part);   // keys in bins above mine
        #pragma unroll
        for (int i = 15; i >= 0; --i) {
            rankS[RIDX(tid * 16 + i)] = running;
            if (running < TOPK && running + c[i] >= TOPK) {   // unique crossing bin
                s_bin = tid * 16 + i;
                s_cntge = running + c[i];
                s_found = 1;
            }
            running += c[i];
        }
    }
    {   // zero hist slice for the next graph replay (reads are done)
        uint4* hz = (uint4*)hb;
        uint4 z = make_uint4(0, 0, 0, 0);
        #pragma unroll
        for (int i = 0; i < 4; ++i) hz[tid * 4 + i] = z;
    }
    __syncthreads();
    if (tid == 0 && (!s_found || s_cntge > CAND_CAP)) s_fb = 1;
    __syncthreads();

    // ==== Phase 2 (fast): scatter keys directly into sorted ranks ====
    if (!s_fb) {
        const unsigned long long thr =
            (unsigned long long)(0x8000u + (unsigned)s_bin) << 48;
        for (int e = tid; e < NPRED; e += 1024) {
            unsigned long long k = keys[e];
            if (k >= thr && (unsigned)(k >> 32) > 0x80000000u) {
                unsigned bin = (unsigned)(k >> 48) - 0x8000u;
                unsigned pos = atomicAdd(&rankS[RIDX(bin)], 1u);
                skeys[pos] = k;
            }
        }
        __syncthreads();
        const int cg = (int)s_cntge;
        for (int t = tid; t < CAND_CAP; t += 1024)
            if (t >= cg) skeys[t] = 0ull;
        __syncthreads();
        // within-bin cleanup: odd-even compare-exchange on equal-bin pairs
        while (true) {
            if (tid == 0) s_flag = 0;
            __syncthreads();
            {
                int i0 = 2 * tid, i1 = i0 + 1;
                if (i1 < cg) {
                    unsigned long long a = skeys[i0], d = skeys[i1];
                    if ((a >> 48) == (d >> 48) && a < d) {
                        skeys[i0] = d; skeys[i1] = a; s_flag = 1;
                    }
                }
            }
            __syncthreads();
            {
                int i0 = 2 * tid + 1, i1 = i0 + 1;
                if (i1 < cg) {
                    unsigned long long a = skeys[i0], d = skeys[i1];
                    if ((a >> 48) == (d >> 48) && a < d) {
                        skeys[i0] = d; skeys[i1] = a; s_flag = 1;
                    }
                }
            }
            __syncthreads();
            if (!s_flag) break;
        }
    }

    // ==== Fallback: exact radix select + compact + bitonic-1024 (rare) ====
    if (s_fb) {
        if (tid == 0) { s_prefix = 0ull; s_r = TOPK; s_done = 0; s_cnt = 0; }
        unsigned long long mask = 0ull;
        for (int pass = 0; pass < 8; ++pass) {
            int shift = 56 - 8 * pass;
            for (int t = tid; t < 32 * 256; t += 1024) whist[t] = 0u;
            __syncthreads();
            unsigned long long pfx = s_prefix;
            unsigned* myh = whist + warp * 256;
            for (int e0 = 0; e0 < NPRED_UP; e0 += 1024) {
                int e = e0 + tid;
                bool inb = e < NPRED;
                unsigned long long k = inb ? keys[e] : 0ull;
                bool act = inb && ((k & mask) == pfx);
                unsigned d = (unsigned)((k >> shift) & 255ull);
                unsigned am = __ballot_sync(FULLMASK, act);
                if (act) {
                    unsigned peers = __match_any_sync(am, d);
                    if (lane == (int)(__ffs(peers) - 1)) myh[d] += __popc(peers);
                }
            }
            __syncthreads();
            if (tid < 256) {
                unsigned s = 0;
                #pragma unroll
                for (int w = 0; w < 32; ++w) s += whist[w * 256 + tid];
                whist[tid] = s;
            }
            __syncthreads();
            if (warp == 0) {
                int r = s_r;
                unsigned s8 = 0;
                #pragma unroll
                for (int i = 0; i < 8; ++i) s8 += whist[lane * 8 + i];
                unsigned i8 = s8;
                #pragma unroll
                for (int off = 1; off < 32; off <<= 1) {
                    unsigned o = __shfl_down_sync(FULLMASK, i8, off);
                    if (lane + off < 32) i8 += o;
                }
                unsigned sufE = i8 - s8;
                if ((int)sufE < r && (int)(sufE + s8) >= r) {
                    unsigned cum = sufE;
                    for (int d = 7; d >= 0; --d) {
                        unsigned cc = whist[lane * 8 + d];
                        if ((int)(cum + cc) >= r) {
                            s_prefix = s_prefix | ((unsigned long long)(lane * 8 + d) << shift);
                            s_r = r - (int)cum;
                            s_done = (cc == (unsigned)(r - (int)cum));
                            break;
                        }
                        cum += cc;
                    }
                }
            }
            mask |= (0xFFull << shift);
            __syncthreads();
            if (s_done) break;
        }
        const unsigned long long T = s_prefix;      // exactly TOPK keys >= T
        for (int e0 = 0; e0 < NPRED_UP; e0 += 1024) {
            int e = e0 + tid;
            bool inb = e < NPRED;
            unsigned long long k = inb ? keys[e] : 0ull;
            bool hit = inb && (k >= T);
            unsigned bm = __ballot_sync(FULLMASK, hit);
            unsigned base = 0;
            if (lane == 0 && bm) base = atomicAdd(&s_cnt, __popc(bm));
            base = __shfl_sync(FULLMASK, base, 0);
            if (hit) {
                int pos = (int)(base + __popc(bm & ((1u << lane) - 1u)));
                if (pos < 1024) skeys[pos] = k;
            }
        }
        __syncthreads();
        for (int t = tid; t < 1024; t += 1024)
            if (t >= s_cnt) skeys[t] = 0ull;
        // bitonic sort 1024 descending
        for (unsigned k = 2; k <= 1024; k <<= 1) {
            for (unsigned j = k >> 1; j > 0; j >>= 1) {
                __syncthreads();
                if (tid < 512) {
                    unsigned e = (((unsigned)tid & ~(j - 1u)) << 1) | ((unsigned)tid & (j - 1u));
                    unsigned p = e | j;
                    unsigned long long x = skeys[e], y = skeys[p];
                    if (((e & k) == 0) ? (x < y) : (x > y)) {
                        skeys[e] = y; skeys[p] = x;
                    }
                }
            }
        }
        __syncthreads();
    }

    // ==== Phase 4: gather det attributes + keep-init ====
    {
        if (tid < TOPK) {
            unsigned long long key = skeys[tid];
            unsigned n = ~((unsigned)key);
            size_t r = (size_t)b * NPRED + n;
            const float* row = in + r * NCH;
            float cx = row[0], cy = row[1], w = row[2], h = row[3], obj = row[4];
            float hw = __fmul_rn(w, 0.5f), hh = __fmul_rn(h, 0.5f);
            float x1 = __fsub_rn(cx, hw), y1 = __fsub_rn(cy, hh);
            float x2 = __fadd_rn(cx, hw), y2 = __fadd_rn(cy, hh);
            sbox[tid]  = make_float4(x1, y1, x2, y2);
            sarea[tid] = __fmul_rn(fmaxf(__fsub_rn(x2, x1), 0.0f),
                                   fmaxf(__fsub_rn(y2, y1), 0.0f));
            sobj[tid]  = obj;
            keepf[tid] = ((unsigned)(key >> 32) > 0x80000000u) ? 1 : 0;
            if (!s_fb) { sconf[tid] = g_conf[r]; scls[tid] = g_cls[r]; }
        } else {
            keepf[tid] = 0;
        }
    }
    if (s_fb) {                             // recompute conf/cls (exact, rare)
        __syncthreads();
        for (int i = warp; i < TOPK; i += 32) {
            unsigned long long key = skeys[i];
            unsigned n = ~((unsigned)key);
            const float* row = in + ((size_t)b * NPRED + n) * NCH;
            unsigned u0 = __float_as_uint(row[5  + lane]);
            unsigned u1 = __float_as_uint(row[37 + lane]);
            unsigned u2 = (lane < 16) ? __float_as_uint(row[69 + lane]) : 0u;
            unsigned m  = __reduce_max_sync(FULLMASK, max(u0, max(u1, u2)));
            unsigned cd = (u0 == m) ? (unsigned)lane
                        : (u1 == m) ? (unsigned)(lane + 32)
                        : ((lane < 16) && (u2 == m)) ? (unsigned)(lane + 64) : 1024u;
            unsigned ci = __reduce_min_sync(FULLMASK, cd);
            if (lane == 0) { sconf[i] = __uint_as_float(m); scls[i] = (int)ci; }
        }
    }
    __syncthreads();

    // ==== Phase 5: class bucketing (stable per-class ordered lists) ====
    for (int c2 = warp; c2 < NCLS; c2 += 32) {
        unsigned n = 0;
        for (int base = 0; base < TOPK; base += 32) {
            int j = base + lane;
            bool mt = (j < TOPK) && (scls[j] == c2);
            n += __popc(__ballot_sync(FULLMASK, mt));
        }
        if (lane == 0) ccnt[c2] = n;
    }
    __syncthreads();
    if (tid == 0) {
        unsigned acc = 0;
        for (int c2 = 0; c2 < NCLS; ++c2) { coff[c2] = acc; acc += ccnt[c2]; }
    }
    __syncthreads();
    for (int c2 = warp; c2 < NCLS; c2 += 32) {
        unsigned off = coff[c2];
        for (int base = 0; base < TOPK; base += 32) {
            int j = base + lane;
            bool mt = (j < TOPK) && (scls[j] == c2);
            unsigned bm = __ballot_sync(FULLMASK, mt);
            if (mt) clist[off + __popc(bm & ((1u << lane) - 1u))] = (unsigned short)j;
            off += __popc(bm);
        }
    }
    __syncthreads();

    // ==== Phase 6: per-class greedy NMS, one warp per class ====
    for (int c2 = warp; c2 < NCLS; c2 += 32) {
        int n = (int)ccnt[c2];
        int base = (int)coff[c2];
        for (int i = 0; i < n; ++i) {
            __syncwarp();
            int pi = clist[base + i];
            if (!keepf[pi]) continue;
            float4 bi = sbox[pi];
            float  ai = sarea[pi];
            for (int jj = i + 1 + lane; jj < n; jj += 32) {
                int pj = clist[base + jj];
                float4 bj = sbox[pj];
                float xx1 = fmaxf(bi.x, bj.x), yy1 = fmaxf(bi.y, bj.y);
                float xx2 = fminf(bi.z, bj.z), yy2 = fminf(bi.w, bj.w);
                float iw  = fmaxf(__fsub_rn(xx2, xx1), 0.0f);
                float ih  = fmaxf(__fsub_rn(yy2, yy1), 0.0f);
                float inter = __fmul_rn(iw, ih);
                float uni   = __fsub_rn(__fadd_rn(ai, sarea[pj]), inter);
                float iou   = __fdiv_rn(inter, __fadd_rn(uni, 1e-16f));
                if (iou > 0.4f) keepf[pj] = 0;
            }
        }
    }
    __syncthreads();

    // ==== Phase 7: masked output (B, 1000, 7) ====
    if (tid < TOPK) {
        float m = keepf[tid] ? 1.0f : 0.0f;
        float4 bx = sbox[tid];
        float* o = out + ((size_t)b * TOPK + tid) * 7;
        o[0] = __fmul_rn(bx.x, m);
        o[1] = __fmul_rn(bx.y, m);
        o[2] = __fmul_rn(bx.z, m);
        o[3] = __fmul_rn(bx.w, m);
        o[4] = __fmul_rn(sobj[tid], m);
        o[5] = __fmul_rn(sconf[tid], m);
        o[6] = __fmul_rn((float)scls[tid], m);
    }
}

extern "C" void kernel_launch(void* const* d_in, const int* in_sizes, int n_in,
                              void* d_out, int out_size) {
    (void)in_sizes; (void)n_in; (void)out_size;
    const float* in  = (const float*)d_in[0];
    float*       out = (float*)d_out;

    score_kernel<<<(NROWS + TA - 1) / TA, TA>>>(in);
    cudaFuncSetAttribute(nms_kernel,
                         cudaFuncAttributeMaxDynamicSharedMemorySize, SMEM_B);
    nms_kernel<<<BATCH, 1024, SMEM_B>>>(in, out);
}

// round 15
// speedup vs baseline: 1.0979x; 1.0979x over previous
#include <cuda_runtime.h>
#include <cstdint>

#define BATCH 16
#define NPRED 22743
#define NCH   85
#define NCLS  80
#define TOPK  1000
#define CAND_CAP 2048
#define FULLMASK 0xFFFFFFFFu
#define NPRED_UP 23552
#define NROWS (BATCH * NPRED)
#define HBINS 16384            // key top-16 bits minus 0x8000, score>0 only

// ---------------- device scratch (no allocations allowed) ----------------
__device__ __align__(16) unsigned long long g_keys[NROWS];
__device__ float    g_conf[NROWS];          // positives only; else 0 (zero-init)
__device__ int      g_cls [NROWS];          // positives only; else 0 (zero-init)
__device__ __align__(16) unsigned g_hist[BATCH * HBINS]; // zero-init; B re-zeroes
// rank-ordered det records (written by B, read by C/D)
__device__ __align__(16) float4 g_rbox [BATCH * TOPK];   // x1,y1,x2,y2
__device__ __align__(16) float4 g_rmeta[BATCH * TOPK];   // area,obj,conf,0
__device__ int            g_rcls [BATCH * TOPK];         // cls | (valid<<31)
__device__ unsigned char  g_keep [BATCH * TOPK];         // written by C

#define NEG_HI 0x407FFFFFu     // ord32(-1.0f)

__device__ __forceinline__ unsigned ord32(float f) {
    unsigned u = __float_as_uint(f);
    return (u & 0x80000000u) ? ~u : (u | 0x80000000u);
}

// ---------------- kernel A: obj-gated score / cls / key / hist ------------
#define TA 256
__global__ void score_kernel(const float* __restrict__ in) {
    __shared__ unsigned short s_list[TA];
    __shared__ float          s_obj [TA];
    __shared__ int s_np;
    const int R0  = blockIdx.x * TA;
    const int tid = threadIdx.x;
    const int lane = tid & 31, warp = tid >> 5;
    if (tid == 0) s_np = 0;
    __syncthreads();

    int gr = R0 + tid;
    bool inr = gr < NROWS;
    float obj = inr ? in[(size_t)gr * NCH + 4] : 0.0f;
    bool pos = inr && (obj >= 0.5f);
    if (inr && !pos) {
        int b = gr / NPRED;
        unsigned n = (unsigned)(gr - b * NPRED);
        g_keys[gr] = ((unsigned long long)NEG_HI << 32) | (unsigned)(~n);
    }
    unsigned bm = __ballot_sync(FULLMASK, pos);
    unsigned base = 0;
    if (lane == 0 && bm) base = atomicAdd(&s_np, __popc(bm));
    base = __shfl_sync(FULLMASK, base, 0);
    if (pos) s_list[base + __popc(bm & ((1u << lane) - 1u))] = (unsigned short)tid;
    s_obj[tid] = obj;
    __syncthreads();

    const int np = s_np;
    for (int i = warp; i < np; i += TA / 32) {
        int lt = (int)s_list[i];
        int r  = R0 + lt;
        const float* row = in + (size_t)r * NCH;
        unsigned u0 = __float_as_uint(row[5  + lane]);
        unsigned u1 = __float_as_uint(row[37 + lane]);
        unsigned u2 = (lane < 16) ? __float_as_uint(row[69 + lane]) : 0u;
        unsigned m  = __reduce_max_sync(FULLMASK, max(u0, max(u1, u2)));
        unsigned cd = (u0 == m) ? (unsigned)lane
                    : (u1 == m) ? (unsigned)(lane + 32)
                    : ((lane < 16) && (u2 == m)) ? (unsigned)(lane + 64) : 1024u;
        unsigned ci = __reduce_min_sync(FULLMASK, cd);
        if (lane == 0) {
            float conf  = __uint_as_float(m);
            float score = __fmul_rn(s_obj[lt], conf);
            int b = r / NPRED;
            unsigned n = (unsigned)(r - b * NPRED);
            unsigned long long key =
                ((unsigned long long)ord32(score) << 32) | (unsigned)(~n);
            g_keys[r] = key;
            g_conf[r] = conf;
            g_cls [r] = (int)ci;
            if (score > 0.0f)
                atomicAdd(&g_hist[b * HBINS + (int)((key >> 48) - 0x8000u)], 1u);
        }
    }
}

// ---------------- kernel B: select + sort + record write ------------------
// SMEM (bytes): cand 16384 -> 16384 | whist 32768 -> 49152 |
//               wtot 128 -> 49280 | wexcl 128 -> 49408
#define SMEM_B 49408

__global__ void __launch_bounds__(1024, 1)
select_kernel(const float* __restrict__ in) {
    extern __shared__ unsigned char smem_raw[];
    unsigned long long* cand  = (unsigned long long*)smem_raw;          // [2048]
    unsigned*           whist = (unsigned*)(cand + CAND_CAP);           // [8192]
    unsigned*           wtot  = whist + 8192;                           // [32]
    unsigned*           wexcl = wtot + 32;                              // [32]
    unsigned* csum = whist;          // [256] phase-1 alias

    __shared__ int s_found, s_chunk, s_bin, s_fb, s_cnt, s_r, s_done;
    __shared__ unsigned s_base, s_cntge;
    __shared__ unsigned long long s_prefix;

    const int b    = blockIdx.x;
    const int tid  = threadIdx.x;
    const int lane = tid & 31;
    const int warp = tid >> 5;
    const unsigned long long* keys = g_keys + (size_t)b * NPRED;
    unsigned* hb = g_hist + b * HBINS;

    if (tid == 0) { s_found = 0; s_fb = 0; s_cnt = 0; }
    __syncthreads();

    // ==== Phase 1: 16-bit prefix of the 1000th-largest positive key ====
    {
        const uint4* hb4 = (const uint4*)hb;
        #pragma unroll
        for (int i = 0; i < 4; ++i) {
            uint4 h4 = hb4[i * 1024 + tid];
            unsigned s = h4.x + h4.y + h4.z + h4.w;
            #pragma unroll
            for (int off = 1; off < 16; off <<= 1)
                s += __shfl_xor_sync(FULLMASK, s, off);
            if ((lane & 15) == 0)
                csum[i * 64 + (tid >> 4)] = s;   // 256 chunks of 64 bins
        }
    }
    __syncthreads();
    unsigned v = 0, incl = 0;
    if (warp < 8) {
        v = csum[tid];
        incl = v;
        #pragma unroll
        for (int off = 1; off < 32; off <<= 1) {
            unsigned o = __shfl_down_sync(FULLMASK, incl, off);
            if (lane + off < 32) incl += o;
        }
        if (lane == 0) wtot[warp] = incl;
    }
    __syncthreads();
    if (warp == 0) {
        unsigned t = (lane < 8) ? wtot[lane] : 0u;
        unsigned i2 = t;
        #pragma unroll
        for (int off = 1; off < 32; off <<= 1) {
            unsigned o = __shfl_down_sync(FULLMASK, i2, off);
            if (lane + off < 32) i2 += o;
        }
        wexcl[lane] = i2 - t;
    }
    __syncthreads();
    if (warp < 8) {
        unsigned sufE = wexcl[warp] + (incl - v);
        if (sufE < TOPK && sufE + v >= TOPK) {
            s_chunk = tid; s_base = sufE; s_found = 1;
        }
    }
    __syncthreads();
    if (s_found && warp == 0) {             // resolve 64 bins in chunk
        int c0 = s_chunk * 64;
        unsigned hlo = hb[c0 + 2 * lane];
        unsigned hhi = hb[c0 + 2 * lane + 1];
        unsigned p = hlo + hhi;
        unsigned ip = p;
        #pragma unroll
        for (int off = 1; off < 32; off <<= 1) {
            unsigned o = __shfl_down_sync(FULLMASK, ip, off);
            if (lane + off < 32) ip += o;
        }
        unsigned sufE = s_base + (ip - p);
        if (sufE < TOPK && sufE + p >= TOPK) {
            if (sufE + hhi >= TOPK) { s_bin = c0 + 2 * lane + 1; s_cntge = sufE + hhi; }
            else                    { s_bin = c0 + 2 * lane;     s_cntge = sufE + p;   }
        }
    }
    __syncthreads();
    {   // zero hist slice for the next graph replay
        uint4* hz = (uint4*)hb;
        uint4 z = make_uint4(0, 0, 0, 0);
        #pragma unroll
        for (int i = 0; i < 4; ++i) hz[i * 1024 + tid] = z;
    }
    if (tid == 0 && (!s_found || s_cntge > CAND_CAP)) s_fb = 1;
    __syncthreads();

    // ==== Phase 2 (fast): warp-aggregated compaction ====
    if (!s_fb) {
        unsigned long long thr = (unsigned long long)(0x8000u + (unsigned)s_bin) << 48;
        for (int e0 = 0; e0 < NPRED_UP; e0 += 1024) {
            int e = e0 + tid;
            bool inb = e < NPRED;
            unsigned long long k = inb ? keys[e] : 0ull;
            bool hit = inb && (k >= thr);
            unsigned bm = __ballot_sync(FULLMASK, hit);
            unsigned base = 0;
            if (lane == 0 && bm) base = atomicAdd(&s_cnt, __popc(bm));
            base = __shfl_sync(FULLMASK, base, 0);
            if (hit) {
                int pos = (int)(base + __popc(bm & ((1u << lane) - 1u)));
                if (pos < CAND_CAP) cand[pos] = k;
            }
        }
        __syncthreads();
        if (tid == 0 && s_cnt > CAND_CAP) s_fb = 1;   // defensive
        __syncthreads();
    }

    // ==== Fallback: exact radix select over all global keys (rare) ====
    if (s_fb) {
        if (tid == 0) { s_prefix = 0ull; s_r = TOPK; s_done = 0; s_cnt = 0; }
        unsigned long long mask = 0ull;
        for (int pass = 0; pass < 8; ++pass) {
            int shift = 56 - 8 * pass;
            for (int t = tid; t < 32 * 256; t += 1024) whist[t] = 0u;
            __syncthreads();
            unsigned long long pfx = s_prefix;
            unsigned* myh = whist + warp * 256;
            for (int e0 = 0; e0 < NPRED_UP; e0 += 1024) {
                int e = e0 + tid;
                bool inb = e < NPRED;
                unsigned long long k = inb ? keys[e] : 0ull;
                bool act = inb && ((k & mask) == pfx);
                unsigned d = (unsigned)((k >> shift) & 255ull);
                unsigned am = __ballot_sync(FULLMASK, act);
                if (act) {
                    unsigned peers = __match_any_sync(am, d);
                    if (lane == (int)(__ffs(peers) - 1)) myh[d] += __popc(peers);
                }
            }
            __syncthreads();
            if (tid < 256) {
                unsigned s = 0;
                #pragma unroll
                for (int w = 0; w < 32; ++w) s += whist[w * 256 + tid];
                whist[tid] = s;
            }
            __syncthreads();
            if (warp == 0) {
                int r = s_r;
                unsigned s8 = 0;
                #pragma unroll
                for (int i = 0; i < 8; ++i) s8 += whist[lane * 8 + i];
                unsigned i8 = s8;
                #pragma unroll
                for (int off = 1; off < 32; off <<= 1) {
                    unsigned o = __shfl_down_sync(FULLMASK, i8, off);
                    if (lane + off < 32) i8 += o;
                }
                unsigned sufE = i8 - s8;
                if ((int)sufE < r && (int)(sufE + s8) >= r) {
                    unsigned cum = sufE;
                    for (int d = 7; d >= 0; --d) {
                        unsigned cc = whist[lane * 8 + d];
                        if ((int)(cum + cc) >= r) {
                            s_prefix = s_prefix | ((unsigned long long)(lane * 8 + d) << shift);
                            s_r = r - (int)cum;
                            s_done = (cc == (unsigned)(r - (int)cum));
                            break;
                        }
                        cum += cc;
                    }
                }
            }
            mask |= (0xFFull << shift);
            __syncthreads();
            if (s_done) break;
        }
        const unsigned long long T = s_prefix;      // exactly TOPK keys >= T
        for (int e0 = 0; e0 < NPRED_UP; e0 += 1024) {
            int e = e0 + tid;
            bool inb = e < NPRED;
            unsigned long long k = inb ? keys[e] : 0ull;
            bool hit = inb && (k >= T);
            unsigned bm = __ballot_sync(FULLMASK, hit);
            unsigned base = 0;
            if (lane == 0 && bm) base = atomicAdd(&s_cnt, __popc(bm));
            base = __shfl_sync(FULLMASK, base, 0);
            if (hit) {
                int pos = (int)(base + __popc(bm & ((1u << lane) - 1u)));
                if (pos < CAND_CAP) cand[pos] = k;
            }
        }
        __syncthreads();
    }

    // ==== Phase 3: pad + bitonic sort 2048 descending ====
    {
        int cnt = s_cnt; if (cnt > CAND_CAP) cnt = CAND_CAP;
        for (int t = tid; t < CAND_CAP; t += 1024)
            if (t >= cnt) cand[t] = 0ull;
    }
    for (unsigned k = 2; k <= CAND_CAP; k <<= 1) {
        for (unsigned j = k >> 1; j > 0; j >>= 1) {
            __syncthreads();
            unsigned i = tid;
            unsigned e = ((i & ~(j - 1u)) << 1) | (i & (j - 1u));
            unsigned p = e | j;
            unsigned long long x = cand[e], y = cand[p];
            bool desc = ((e & k) == 0);
            if (desc ? (x < y) : (x > y)) { cand[e] = y; cand[p] = x; }
        }
    }
    __syncthreads();

    // ==== Phase 4: gather + write rank-ordered records ====
    if (tid < TOPK) {
        unsigned long long key = cand[tid];
        unsigned n = ~((unsigned)key);
        size_t r = (size_t)b * NPRED + n;
        const float* row = in + r * NCH;
        float cx = row[0], cy = row[1], w = row[2], h = row[3], obj = row[4];
        float hw = __fmul_rn(w, 0.5f), hh = __fmul_rn(h, 0.5f);
        float x1 = __fsub_rn(cx, hw), y1 = __fsub_rn(cy, hh);
        float x2 = __fadd_rn(cx, hw), y2 = __fadd_rn(cy, hh);
        float area = __fmul_rn(fmaxf(__fsub_rn(x2, x1), 0.0f),
                               fmaxf(__fsub_rn(y2, y1), 0.0f));
        bool valid = ((unsigned)(key >> 32) > 0x80000000u);
        int o = b * TOPK + tid;
        g_rbox [o] = make_float4(x1, y1, x2, y2);
        g_rmeta[o] = make_float4(area, obj, g_conf[r], 0.0f);
        g_rcls [o] = g_cls[r] | (valid ? (int)0x80000000 : 0);
    }
}

// ---------------- kernel C: per-(image,class) greedy NMS ------------------
__global__ void __launch_bounds__(32)
nmsc_kernel() {
    __shared__ unsigned short list[TOPK];
    __shared__ float4 lbox[TOPK];
    __shared__ float  larea[TOPK];
    __shared__ unsigned char lkeep[TOPK];
    __shared__ int s_n;

    const int cls  = blockIdx.x;
    const int img  = blockIdx.y;
    const int lane = threadIdx.x;
    const int rb   = img * TOPK;

    if (lane == 0) s_n = 0;
    __syncwarp();

    // membership scan (rank order preserved)
    for (int base = 0; base < 1024; base += 32) {
        int det = base + lane;
        int cv = 0;
        bool mt = false;
        if (det < TOPK) {
            cv = g_rcls[rb + det];
            mt = ((cv & 0x7FFFFFFF) == cls);
        }
        unsigned bm = __ballot_sync(FULLMASK, mt);
        if (mt) {
            int pos = s_n + __popc(bm & ((1u << lane) - 1u));
            list[pos] = (unsigned short)det;
            lkeep[pos] = (cv < 0) ? 1 : 0;   // valid bit in sign
        }
        __syncwarp();
        if (lane == 0) s_n += __popc(bm);
        __syncwarp();
    }
    const int n = s_n;
    if (n == 0) return;

    // stage member boxes/areas
    for (int i = lane; i < n; i += 32) {
        int det = (int)list[i];
        lbox[i]  = g_rbox[rb + det];
        larea[i] = g_rmeta[rb + det].x;
    }
    __syncwarp();

    // greedy sweep (exact reference semantics)
    for (int i = 0; i < n; ++i) {
        __syncwarp();
        if (!lkeep[i]) continue;
        float4 bi = lbox[i];
        float  ai = larea[i];
        for (int jj = i + 1 + lane; jj < n; jj += 32) {
            float4 bj = lbox[jj];
            float xx1 = fmaxf(bi.x, bj.x), yy1 = fmaxf(bi.y, bj.y);
            float xx2 = fminf(bi.z, bj.z), yy2 = fminf(bi.w, bj.w);
            float iw  = fmaxf(__fsub_rn(xx2, xx1), 0.0f);
            float ih  = fmaxf(__fsub_rn(yy2, yy1), 0.0f);
            float inter = __fmul_rn(iw, ih);
            float uni   = __fsub_rn(__fadd_rn(ai, larea[jj]), inter);
            float iou   = __fdiv_rn(inter, __fadd_rn(uni, 1e-16f));
            if (iou > 0.4f) lkeep[jj] = 0;
        }
    }
    __syncwarp();
    for (int i = lane; i < n; i += 32)
        g_keep[rb + (int)list[i]] = lkeep[i];
}

// ---------------- kernel D: masked output (B, 1000, 7) --------------------
__global__ void out_kernel(float* __restrict__ out) {
    int g = blockIdx.x * blockDim.x + threadIdx.x;
    if (g >= BATCH * TOPK) return;
    float m = g_keep[g] ? 1.0f : 0.0f;
    float4 bx = g_rbox[g];
    float4 mt = g_rmeta[g];
    int cls = g_rcls[g] & 0x7FFFFFFF;
    float* o = out + (size_t)g * 7;
    o[0] = __fmul_rn(bx.x, m);
    o[1] = __fmul_rn(bx.y, m);
    o[2] = __fmul_rn(bx.z, m);
    o[3] = __fmul_rn(bx.w, m);
    o[4] = __fmul_rn(mt.y, m);
    o[5] = __fmul_rn(mt.z, m);
    o[6] = __fmul_rn((float)cls, m);
}

extern "C" void kernel_launch(void* const* d_in, const int* in_sizes, int n_in,
                              void* d_out, int out_size) {
    (void)in_sizes; (void)n_in; (void)out_size;
    const float* in  = (const float*)d_in[0];
    float*       out = (float*)d_out;

    score_kernel<<<(NROWS + TA - 1) / TA, TA>>>(in);
    cudaFuncSetAttribute(select_kernel,
                         cudaFuncAttributeMaxDynamicSharedMemorySize, SMEM_B);
    select_kernel<<<BATCH, 1024, SMEM_B>>>(in);
    nmsc_kernel<<<dim3(NCLS, BATCH), 32>>>();
    out_kernel<<<(BATCH * TOPK + 255) / 256, 256>>>(out);
}

// round 16
// speedup vs baseline: 1.3016x; 1.1855x over previous
#include <cuda_runtime.h>
#include <cstdint>

#define BATCH 16
#define NPRED 22743
#define NCH   85
#define NCLS  80
#define TOPK  1000
#define CAND_CAP 2048
#define FULLMASK 0xFFFFFFFFu
#define NPRED_UP 23552
#define NROWS (BATCH * NPRED)
#define HBINS 16384            // key top-16 bits minus 0x8000, score>0 only
#define RIDX(d) ((d) + ((d) >> 4))   // stride-17 padding -> conflict-free

// ---------------- device scratch (no allocations allowed) ----------------
__device__ __align__(16) unsigned long long g_keys[NROWS];
__device__ float    g_conf[NROWS];          // positives only; else 0 (zero-init)
__device__ int      g_cls [NROWS];          // positives only; else 0 (zero-init)
__device__ __align__(16) unsigned g_hist[BATCH * HBINS]; // zero-init; B re-zeroes
// rank-ordered det records (written by B, read by C)
__device__ __align__(16) float4 g_rbox [BATCH * TOPK];   // x1,y1,x2,y2
__device__ __align__(16) float4 g_rmeta[BATCH * TOPK];   // area,obj,conf,0
__device__ int            g_rcls [BATCH * TOPK];         // cls | (valid<<31)

#define NEG_HI 0x407FFFFFu     // ord32(-1.0f)

__device__ __forceinline__ unsigned ord32(float f) {
    unsigned u = __float_as_uint(f);
    return (u & 0x80000000u) ? ~u : (u | 0x80000000u);
}

// ---------------- kernel A: obj-gated score / cls / key / hist ------------
#define TA 256
__global__ void score_kernel(const float* __restrict__ in) {
    __shared__ unsigned short s_list[TA];
    __shared__ float          s_obj [TA];
    __shared__ int s_np;
    const int R0  = blockIdx.x * TA;
    const int tid = threadIdx.x;
    const int lane = tid & 31, warp = tid >> 5;
    if (tid == 0) s_np = 0;
    __syncthreads();

    int gr = R0 + tid;
    bool inr = gr < NROWS;
    float obj = inr ? in[(size_t)gr * NCH + 4] : 0.0f;
    bool pos = inr && (obj >= 0.5f);
    if (inr && !pos) {
        int b = gr / NPRED;
        unsigned n = (unsigned)(gr - b * NPRED);
        g_keys[gr] = ((unsigned long long)NEG_HI << 32) | (unsigned)(~n);
    }
    unsigned bm = __ballot_sync(FULLMASK, pos);
    unsigned base = 0;
    if (lane == 0 && bm) base = atomicAdd(&s_np, __popc(bm));
    base = __shfl_sync(FULLMASK, base, 0);
    if (pos) s_list[base + __popc(bm & ((1u << lane) - 1u))] = (unsigned short)tid;
    s_obj[tid] = obj;
    __syncthreads();

    const int np = s_np;
    for (int i = warp; i < np; i += TA / 32) {
        int lt = (int)s_list[i];
        int r  = R0 + lt;
        const float* row = in + (size_t)r * NCH;
        unsigned u0 = __float_as_uint(row[5  + lane]);
        unsigned u1 = __float_as_uint(row[37 + lane]);
        unsigned u2 = (lane < 16) ? __float_as_uint(row[69 + lane]) : 0u;
        unsigned m  = __reduce_max_sync(FULLMASK, max(u0, max(u1, u2)));
        unsigned cd = (u0 == m) ? (unsigned)lane
                    : (u1 == m) ? (unsigned)(lane + 32)
                    : ((lane < 16) && (u2 == m)) ? (unsigned)(lane + 64) : 1024u;
        unsigned ci = __reduce_min_sync(FULLMASK, cd);
        if (lane == 0) {
            float conf  = __uint_as_float(m);
            float score = __fmul_rn(s_obj[lt], conf);
            int b = r / NPRED;
            unsigned n = (unsigned)(r - b * NPRED);
            unsigned long long key =
                ((unsigned long long)ord32(score) << 32) | (unsigned)(~n);
            g_keys[r] = key;
            g_conf[r] = conf;
            g_cls [r] = (int)ci;
            if (score > 0.0f)
                atomicAdd(&g_hist[b * HBINS + (int)((key >> 48) - 0x8000u)], 1u);
        }
    }
}

// ---------------- kernel B: counting-rank select + record write -----------
// SMEM (bytes, cumulative): tmp 16384 -> 16384 | skeys 16384 -> 32768 |
//   baseS 69632 -> 102400 | fillS 69632 -> 172032 | wtot 128 -> 172160 |
//   wexcl 128 -> 172288
#define SMEM_B 172288

__global__ void __launch_bounds__(1024, 1)
select_kernel(const float* __restrict__ in) {
    extern __shared__ unsigned char smem_raw[];
    unsigned long long* tmp   = (unsigned long long*)smem_raw;          // [2048]
    unsigned long long* skeys = tmp + CAND_CAP;                         // [2048]
    unsigned*           baseS = (unsigned*)(skeys + CAND_CAP);          // [17408]
    unsigned*           fillS = baseS + 17408;                          // [17408]
    unsigned*           wtot  = fillS + 17408;                          // [32]
    unsigned*           wexcl = wtot + 32;                              // [32]
    unsigned*           whist = baseS;     // fallback alias (32*256 u32)

    __shared__ int s_found, s_bin, s_fb, s_cnt, s_r, s_done;
    __shared__ unsigned s_cntge;
    __shared__ unsigned long long s_prefix;

    const int b    = blockIdx.x;
    const int tid  = threadIdx.x;
    const int lane = tid & 31;
    const int warp = tid >> 5;
    const unsigned long long* keys = g_keys + (size_t)b * NPRED;
    unsigned* hb = g_hist + b * HBINS;

    if (tid == 0) { s_found = 0; s_fb = 0; s_cnt = 0; }
    __syncthreads();

    // ==== Phase 1: per-bin suffix scan -> base ranks + threshold bin ====
    unsigned c[16];
    {
        const uint4* hb4 = (const uint4*)hb;
        #pragma unroll
        for (int i = 0; i < 4; ++i) {
            uint4 h = hb4[tid * 4 + i];
            c[i*4] = h.x; c[i*4+1] = h.y; c[i*4+2] = h.z; c[i*4+3] = h.w;
        }
    }
    unsigned part = 0;
    #pragma unroll
    for (int i = 0; i < 16; ++i) part += c[i];
    unsigned incl = part;
    #pragma unroll
    for (int off = 1; off < 32; off <<= 1) {
        unsigned o = __shfl_down_sync(FULLMASK, incl, off);
        if (lane + off < 32) incl += o;
    }
    if (lane == 0) wtot[warp] = incl;
    __syncthreads();
    if (warp == 0) {
        unsigned t = wtot[lane];
        unsigned i2 = t;
        #pragma unroll
        for (int off = 1; off < 32; off <<= 1) {
            unsigned o = __shfl_down_sync(FULLMASK, i2, off);
            if (lane + off < 32) i2 += o;
        }
        wexcl[lane] = i2 - t;
    }
    __syncthreads();
    {
        unsigned running = wexcl[warp] + (incl - part);   // keys in bins above
        #pragma unroll
        for (int i = 15; i >= 0; --i) {
            int bin = tid * 16 + i;
            baseS[RIDX(bin)] = running;
            fillS[RIDX(bin)] = running;                   // scatter cursor
            if (running < TOPK && running + c[i] >= TOPK) {
                s_bin = bin;
                s_cntge = running + c[i];
                s_found = 1;
            }
            running += c[i];
        }
    }
    {   // zero hist slice for the next graph replay
        uint4* hz = (uint4*)hb;
        uint4 z = make_uint4(0, 0, 0, 0);
        #pragma unroll
        for (int i = 0; i < 4; ++i) hz[tid * 4 + i] = z;
    }
    __syncthreads();
    if (tid == 0 && (!s_found || s_cntge > CAND_CAP)) s_fb = 1;
    __syncthreads();

    if (!s_fb) {
        // ==== Phase 2: scatter candidates into contiguous bin segments ====
        const unsigned long long thr =
            (unsigned long long)(0x8000u + (unsigned)s_bin) << 48;
        for (int e = tid; e < NPRED; e += 1024) {
            unsigned long long k = keys[e];
            if (k >= thr && (unsigned)(k >> 32) > 0x80000000u) {
                unsigned bin = (unsigned)(k >> 48) - 0x8000u;
                unsigned slot = atomicAdd(&fillS[RIDX(bin)], 1u);
                tmp[slot] = k;
            }
        }
        __syncthreads();
        // ==== Phase 3: exact position by counting larger keys in segment ====
        const int cg = (int)s_cntge;       // >= TOPK guaranteed (crossing bin)
        for (int t = tid; t < cg; t += 1024) {
            unsigned long long k = tmp[t];
            unsigned bin = (unsigned)(k >> 48) - 0x8000u;
            int base = (int)baseS[RIDX(bin)];
            int end  = (int)fillS[RIDX(bin)];
            int cnt = 0;
            for (int s = base; s < end; ++s)           // broadcast smem reads
                cnt += (tmp[s] > k) ? 1 : 0;
            skeys[base + cnt] = k;                      // unique (keys distinct)
        }
        __syncthreads();
    } else {
        // ==== Fallback: exact radix select + bitonic-1024 (rare) ====
        if (tid == 0) { s_prefix = 0ull; s_r = TOPK; s_done = 0; s_cnt = 0; }
        unsigned long long mask = 0ull;
        for (int pass = 0; pass < 8; ++pass) {
            int shift = 56 - 8 * pass;
            for (int t = tid; t < 32 * 256; t += 1024) whist[t] = 0u;
            __syncthreads();
            unsigned long long pfx = s_prefix;
            unsigned* myh = whist + warp * 256;
            for (int e0 = 0; e0 < NPRED_UP; e0 += 1024) {
                int e = e0 + tid;
                bool inb = e < NPRED;
                unsigned long long k = inb ? keys[e] : 0ull;
                bool act = inb && ((k & mask) == pfx);
                unsigned d = (unsigned)((k >> shift) & 255ull);
                unsigned am = __ballot_sync(FULLMASK, act);
                if (act) {
                    unsigned peers = __match_any_sync(am, d);
                    if (lane == (int)(__ffs(peers) - 1)) myh[d] += __popc(peers);
                }
            }
            __syncthreads();
            if (tid < 256) {
                unsigned s = 0;
                #pragma unroll
                for (int w = 0; w < 32; ++w) s += whist[w * 256 + tid];
                whist[tid] = s;
            }
            __syncthreads();
            if (warp == 0) {
                int r = s_r;
                unsigned s8 = 0;
                #pragma unroll
                for (int i = 0; i < 8; ++i) s8 += whist[lane * 8 + i];
                unsigned i8 = s8;
                #pragma unroll
                for (int off = 1; off < 32; off <<= 1) {
                    unsigned o = __shfl_down_sync(FULLMASK, i8, off);
                    if (lane + off < 32) i8 += o;
                }
                unsigned sufE = i8 - s8;
                if ((int)sufE < r && (int)(sufE + s8) >= r) {
                    unsigned cum = sufE;
                    for (int d = 7; d >= 0; --d) {
                        unsigned cc = whist[lane * 8 + d];
                        if ((int)(cum + cc) >= r) {
                            s_prefix = s_prefix | ((unsigned long long)(lane * 8 + d) << shift);
                            s_r = r - (int)cum;
                            s_done = (cc == (unsigned)(r - (int)cum));
                            break;
                        }
                        cum += cc;
                    }
                }
            }
            mask |= (0xFFull << shift);
            __syncthreads();
            if (s_done) break;
        }
        const unsigned long long T = s_prefix;          // exactly TOPK keys >= T
        for (int e0 = 0; e0 < NPRED_UP; e0 += 1024) {
            int e = e0 + tid;
            bool inb = e < NPRED;
            unsigned long long k = inb ? keys[e] : 0ull;
            bool hit = inb && (k >= T);
            unsigned bm = __ballot_sync(FULLMASK, hit);
            unsigned base = 0;
            if (lane == 0 && bm) base = atomicAdd(&s_cnt, __popc(bm));
            base = __shfl_sync(FULLMASK, base, 0);
            if (hit) {
                int pos = (int)(base + __popc(bm & ((1u << lane) - 1u)));
                if (pos < 1024) skeys[pos] = k;
            }
        }
        __syncthreads();
        for (int t = tid; t < 1024; t += 1024)
            if (t >= s_cnt) skeys[t] = 0ull;
        for (unsigned k = 2; k <= 1024; k <<= 1) {
            for (unsigned j = k >> 1; j > 0; j >>= 1) {
                __syncthreads();
                if (tid < 512) {
                    unsigned e = (((unsigned)tid & ~(j - 1u)) << 1) | ((unsigned)tid & (j - 1u));
                    unsigned p = e | j;
                    unsigned long long x = skeys[e], y = skeys[p];
                    if (((e & k) == 0) ? (x < y) : (x > y)) {
                        skeys[e] = y; skeys[p] = x;
                    }
                }
            }
        }
        __syncthreads();
    }

    // ==== Phase 4: gather + write rank-ordered records ====
    if (tid < TOPK) {
        unsigned long long key = skeys[tid];    // first TOPK are always real keys
        unsigned n = ~((unsigned)key);
        size_t r = (size_t)b * NPRED + n;
        const float* row = in + r * NCH;
        float cx = row[0], cy = row[1], w = row[2], h = row[3], obj = row[4];
        float hw = __fmul_rn(w, 0.5f), hh = __fmul_rn(h, 0.5f);
        float x1 = __fsub_rn(cx, hw), y1 = __fsub_rn(cy, hh);
        float x2 = __fadd_rn(cx, hw), y2 = __fadd_rn(cy, hh);
        float area = __fmul_rn(fmaxf(__fsub_rn(x2, x1), 0.0f),
                               fmaxf(__fsub_rn(y2, y1), 0.0f));
        bool valid = ((unsigned)(key >> 32) > 0x80000000u);
        int o = b * TOPK + tid;
        g_rbox [o] = make_float4(x1, y1, x2, y2);
        g_rmeta[o] = make_float4(area, obj, g_conf[r], 0.0f);
        g_rcls [o] = g_cls[r] | (valid ? (int)0x80000000 : 0);
    }
}

// ---------------- kernel C: per-(image,class) NMS + fused output ----------
__global__ void __launch_bounds__(32)
nmsc_kernel(float* __restrict__ out) {
    __shared__ unsigned short list[TOPK];
    __shared__ float4 lbox[TOPK];
    __shared__ float  larea[TOPK];
    __shared__ unsigned char lkeep[TOPK];
    __shared__ int s_n;

    const int cls  = blockIdx.x;
    const int img  = blockIdx.y;
    const int lane = threadIdx.x;
    const int rb   = img * TOPK;

    if (lane == 0) s_n = 0;
    __syncwarp();

    // membership scan (rank order preserved)
    for (int base = 0; base < 1024; base += 32) {
        int det = base + lane;
        int cv = 0;
        bool mt = false;
        if (det < TOPK) {
            cv = g_rcls[rb + det];
            mt = ((cv & 0x7FFFFFFF) == cls);
        }
        unsigned bm = __ballot_sync(FULLMASK, mt);
        if (mt) {
            int pos = s_n + __popc(bm & ((1u << lane) - 1u));
            list[pos] = (unsigned short)det;
            lkeep[pos] = (cv < 0) ? 1 : 0;   // valid bit in sign
        }
        __syncwarp();
        if (lane == 0) s_n += __popc(bm);
        __syncwarp();
    }
    const int n = s_n;
    if (n == 0) return;

    // stage member boxes/areas
    for (int i = lane; i < n; i += 32) {
        int det = (int)list[i];
        lbox[i]  = g_rbox[rb + det];
        larea[i] = g_rmeta[rb + det].x;
    }
    __syncwarp();

    // greedy sweep (exact reference semantics)
    for (int i = 0; i < n; ++i) {
        __syncwarp();
        if (!lkeep[i]) continue;
        float4 bi = lbox[i];
        float  ai = larea[i];
        for (int jj = i + 1 + lane; jj < n; jj += 32) {
            float4 bj = lbox[jj];
            float xx1 = fmaxf(bi.x, bj.x), yy1 = fmaxf(bi.y, bj.y);
            float xx2 = fminf(bi.z, bj.z), yy2 = fminf(bi.w, bj.w);
            float iw  = fmaxf(__fsub_rn(xx2, xx1), 0.0f);
            float ih  = fmaxf(__fsub_rn(yy2, yy1), 0.0f);
            float inter = __fmul_rn(iw, ih);
            float uni   = __fsub_rn(__fadd_rn(ai, larea[jj]), inter);
            float iou   = __fdiv_rn(inter, __fadd_rn(uni, 1e-16f));
            if (iou > 0.4f) lkeep[jj] = 0;
        }
    }
    __syncwarp();

    // fused masked output: each CTA writes its members' rows
    for (int i = lane; i < n; i += 32) {
        int det = (int)list[i];
        float m = lkeep[i] ? 1.0f : 0.0f;
        float4 bx = lbox[i];
        float4 mt = g_rmeta[rb + det];
        float* o = out + ((size_t)(rb + det)) * 7;
        o[0] = __fmul_rn(bx.x, m);
        o[1] = __fmul_rn(bx.y, m);
        o[2] = __fmul_rn(bx.z, m);
        o[3] = __fmul_rn(bx.w, m);
        o[4] = __fmul_rn(mt.y, m);
        o[5] = __fmul_rn(mt.z, m);
        o[6] = __fmul_rn((float)cls, m);
    }
}

extern "C" void kernel_launch(void* const* d_in, const int* in_sizes, int n_in,
                              void* d_out, int out_size) {
    (void)in_sizes; (void)n_in; (void)out_size;
    const float* in  = (const float*)d_in[0];
    float*       out = (float*)d_out;

    score_kernel<<<(NROWS + TA - 1) / TA, TA>>>(in);
    cudaFuncSetAttribute(select_kernel,
                         cudaFuncAttributeMaxDynamicSharedMemorySize, SMEM_B);
    select_kernel<<<BATCH, 1024, SMEM_B>>>(in);
    nmsc_kernel<<<dim3(NCLS, BATCH), 32>>>(out);
}